// round 16
// baseline (speedup 1.0000x reference)
#include <cuda_runtime.h>
#include <cstdint>

// Packed {scale (lo 32b), 1/scale (hi 32b)}. Zero means "not yet published".
// scale > 0 always, so the value is its own ready flag.
__device__ volatile unsigned long long g_scale_packed;

#define NCHUNK       4
#define CHUNK_BYTES  16384                     // 4096 floats = one k-iter region
#define SMEM_MBAR_OFF (NCHUNK * CHUNK_BYTES)   // 65536
#define SMEM_RED_OFF  (SMEM_MBAR_OFF + 64)     // barriers padded to 64B
#define SMEM_TOTAL    (SMEM_RED_OFF + 8 * 4 * 4 + 64)   // 65792

__device__ __forceinline__ uint32_t smem_u32(const void* p) {
    uint32_t a;
    asm("{ .reg .u64 t; cvta.to.shared.u64 t, %1; cvt.u32.u64 %0, t; }"
        : "=r"(a) : "l"(p));
    return a;
}

__device__ __forceinline__ void mbar_init(uint32_t addr, uint32_t cnt) {
    asm volatile("mbarrier.init.shared.b64 [%0], %1;" :: "r"(addr), "r"(cnt) : "memory");
}
__device__ __forceinline__ void mbar_expect_tx(uint32_t addr, uint32_t bytes) {
    asm volatile("mbarrier.arrive.expect_tx.shared.b64 _, [%0], %1;"
                 :: "r"(addr), "r"(bytes) : "memory");
}
__device__ __forceinline__ void tma_1d(uint32_t dst, const void* src,
                                       uint32_t bytes, uint32_t mbar) {
    asm volatile(
        "cp.async.bulk.shared::cta.global.mbarrier::complete_tx::bytes [%0], [%1], %2, [%3];"
        :: "r"(dst), "l"(src), "r"(bytes), "r"(mbar) : "memory");
}
__device__ __forceinline__ void mbar_wait(uint32_t addr, uint32_t parity) {
    asm volatile(
        "{\n\t"
        ".reg .pred P1;\n\t"
        "WAIT_LOOP_%=:\n\t"
        "mbarrier.try_wait.parity.acquire.cta.shared::cta.b64 P1, [%0], %1, 0x989680;\n\t"
        "@P1 bra.uni WAIT_DONE_%=;\n\t"
        "bra.uni WAIT_LOOP_%=;\n\t"
        "WAIT_DONE_%=:\n\t"
        "}"
        :: "r"(addr), "r"(parity) : "memory");
}

// ---------------------------------------------------------------------------
// Grid 8193, one batch row per worker CTA, TMA-bulk pipeline:
//   block 0       : compute scale = max|W|/7, publish packed {s, 1/s}.
//   blocks 1..8192: issue 4x cp.async.bulk (16KB contiguous chunks of the
//                   row) upfront into smem with per-chunk mbarriers, preload
//                   + dequant all weights during the fill, then consume each
//                   chunk via conflict-free LDS.128 + FMA as it lands.
// In-flight DRAM bytes/SM = 3 CTAs x 64KB = 192KB (vs 4KB with LDG pipeline)
// with only ~40 registers/thread; occupancy is smem-limited at 3 CTAs/SM.
//
// x layout: [B=8192, 16384 floats/row]. Chunk c holds floats
// [c*4096,(c+1)*4096). Thread t pools feature-pair fp = t + c*256 via 4
// float4 LDS at loff, +16, +256, +272 floats;
// loff = (t>>5)*512 + ((t>>2)&7)*32 + (t&3)*4.
// ---------------------------------------------------------------------------
__global__ void __launch_bounds__(256)
fused_pool_linear_softmax_kernel(const float* __restrict__ x,
                                 const float* __restrict__ W,
                                 const float* __restrict__ bias,
                                 float* __restrict__ out) {
    extern __shared__ __align__(128) char smem[];
    const int t = threadIdx.x;

    // ---------------- block 0: scale producer ----------------
    if (blockIdx.x == 0) {
        float* s_warp = reinterpret_cast<float*>(smem);
        const float4* __restrict__ W4 = reinterpret_cast<const float4*>(W);
        float m = 0.0f;
        #pragma unroll
        for (int k = 0; k < 8; k++) {
            const float4 w = W4[t + k * 256];
            m = fmaxf(m, fmaxf(fmaxf(fabsf(w.x), fabsf(w.y)),
                               fmaxf(fabsf(w.z), fabsf(w.w))));
        }
        #pragma unroll
        for (int off = 16; off > 0; off >>= 1)
            m = fmaxf(m, __shfl_xor_sync(0xFFFFFFFFu, m, off));
        if ((t & 31) == 0) s_warp[t >> 5] = m;
        __syncthreads();
        if (t == 0) {
            float mm = fmaxf(fmaxf(fmaxf(s_warp[0], s_warp[1]),
                                   fmaxf(s_warp[2], s_warp[3])),
                             fmaxf(fmaxf(s_warp[4], s_warp[5]),
                                   fmaxf(s_warp[6], s_warp[7])));
            const float scale = mm / 7.0f;
            const float inv_scale = 1.0f / scale;
            const unsigned long long packed =
                ((unsigned long long)__float_as_uint(inv_scale) << 32) |
                (unsigned long long)__float_as_uint(scale);
            g_scale_packed = packed;
        }
        return;
    }

    // ---------------- worker: one row ----------------
    float* buf = reinterpret_cast<float*>(smem);
    const uint32_t sb = smem_u32(smem);
    const uint32_t mb = sb + SMEM_MBAR_OFF;
    float (*s_red)[4] = reinterpret_cast<float(*)[4]>(smem + SMEM_RED_OFF);

    const int row = blockIdx.x - 1;
    const float* __restrict__ src = x + (size_t)row * 16384;

    if (t == 0) {
        #pragma unroll
        for (int c = 0; c < NCHUNK; c++) mbar_init(mb + 8 * c, 1);
    }

    // weight preloads overlap the barrier init / sync
    const int wb = t * 2;
    float2 wv[4][4];
    #pragma unroll
    for (int k = 0; k < 4; k++) {
        const int f2 = wb + k * 512;
        wv[k][0] = *reinterpret_cast<const float2*>(&W[f2]);
        wv[k][1] = *reinterpret_cast<const float2*>(&W[2048 + f2]);
        wv[k][2] = *reinterpret_cast<const float2*>(&W[4096 + f2]);
        wv[k][3] = *reinterpret_cast<const float2*>(&W[6144 + f2]);
    }
    const float4 bias4 = *reinterpret_cast<const float4*>(bias);

    __syncthreads();   // barriers initialized before anyone waits / TMA lands

    if (t == 0) {
        #pragma unroll
        for (int c = 0; c < NCHUNK; c++) {
            mbar_expect_tx(mb + 8 * c, CHUNK_BYTES);
            tma_1d(sb + c * CHUNK_BYTES, src + c * 4096, CHUNK_BYTES, mb + 8 * c);
        }
    }

    // spin for the packed scale while TMAs stream (value is its own flag)
    unsigned long long v = g_scale_packed;
    while (v == 0ull) v = g_scale_packed;
    const float scale     = __uint_as_float((unsigned int)v);
    const float inv_scale = __uint_as_float((unsigned int)(v >> 32));

    // dequantize all weights once (half-to-even; clip(-8,7) never binds)
    #pragma unroll
    for (int k = 0; k < 4; k++) {
        #pragma unroll
        for (int o = 0; o < 4; o++) {
            wv[k][o].x = rintf(wv[k][o].x * inv_scale) * scale;
            wv[k][o].y = rintf(wv[k][o].y * inv_scale) * scale;
        }
    }

    const int loff = (t >> 5) * 512 + ((t >> 2) & 7) * 32 + (t & 3) * 4;
    float l0 = 0.0f, l1 = 0.0f, l2 = 0.0f, l3 = 0.0f;

    #pragma unroll
    for (int c = 0; c < NCHUNK; c++) {
        mbar_wait(mb + 8 * c, 0);

        const float4* p = reinterpret_cast<const float4*>(buf + c * 4096 + loff);
        const float4 a0 = p[0];     // (d0, h0)
        const float4 a1 = p[4];     // (d0, h1)
        const float4 a2 = p[64];    // (d1, h0)
        const float4 a3 = p[68];    // (d1, h1)

        const float m0 = fmaxf(fmaxf(fmaxf(a0.x, a0.y), fmaxf(a1.x, a1.y)),
                               fmaxf(fmaxf(a2.x, a2.y), fmaxf(a3.x, a3.y)));
        const float m1 = fmaxf(fmaxf(fmaxf(a0.z, a0.w), fmaxf(a1.z, a1.w)),
                               fmaxf(fmaxf(a2.z, a2.w), fmaxf(a3.z, a3.w)));

        l0 = fmaf(m0, wv[c][0].x, fmaf(m1, wv[c][0].y, l0));
        l1 = fmaf(m0, wv[c][1].x, fmaf(m1, wv[c][1].y, l1));
        l2 = fmaf(m0, wv[c][2].x, fmaf(m1, wv[c][2].y, l2));
        l3 = fmaf(m0, wv[c][3].x, fmaf(m1, wv[c][3].y, l3));
    }

    // warp reduce 4 accumulators
    #pragma unroll
    for (int off = 16; off > 0; off >>= 1) {
        l0 += __shfl_xor_sync(0xFFFFFFFFu, l0, off);
        l1 += __shfl_xor_sync(0xFFFFFFFFu, l1, off);
        l2 += __shfl_xor_sync(0xFFFFFFFFu, l2, off);
        l3 += __shfl_xor_sync(0xFFFFFFFFu, l3, off);
    }
    const int wid = t >> 5;
    if ((t & 31) == 0) {
        s_red[wid][0] = l0;  s_red[wid][1] = l1;
        s_red[wid][2] = l2;  s_red[wid][3] = l3;
    }
    __syncthreads();

    if (t == 0) {
        float r0 = bias4.x, r1 = bias4.y, r2 = bias4.z, r3 = bias4.w;
        #pragma unroll
        for (int w = 0; w < 8; w++) {
            r0 += s_red[w][0];
            r1 += s_red[w][1];
            r2 += s_red[w][2];
            r3 += s_red[w][3];
        }
        const float mx = fmaxf(fmaxf(r0, r1), fmaxf(r2, r3));
        const float e0 = __expf(r0 - mx);
        const float e1 = __expf(r1 - mx);
        const float e2 = __expf(r2 - mx);
        const float e3 = __expf(r3 - mx);
        const float inv = 1.0f / (e0 + e1 + e2 + e3);
        float4 r = make_float4(e0 * inv, e1 * inv, e2 * inv, e3 * inv);
        *reinterpret_cast<float4*>(out + (size_t)row * 4) = r;
    }
}

extern "C" void kernel_launch(void* const* d_in, const int* in_sizes, int n_in,
                              void* d_out, int out_size) {
    const float* x = (const float*)d_in[0];   // [8192,4,16,16,16]
    const float* W = (const float*)d_in[1];   // [4,2048]
    const float* b = (const float*)d_in[2];   // [4]
    float* out = (float*)d_out;               // [8192,4]

    static bool attr_set = false;
    if (!attr_set) {
        cudaFuncSetAttribute(fused_pool_linear_softmax_kernel,
                             cudaFuncAttributeMaxDynamicSharedMemorySize,
                             SMEM_TOTAL);
        attr_set = true;
    }
    fused_pool_linear_softmax_kernel<<<8193, 256, SMEM_TOTAL>>>(x, W, b, out);
}

// round 17
// speedup vs baseline: 1.0126x; 1.0126x over previous
#include <cuda_runtime.h>
#include <cuda_bf16.h>
#include <float.h>

// Packed {scale (lo 32b), 1/scale (hi 32b)}. Zero means "not yet published".
// scale > 0 always, so the published value is never 0 — the value is its own
// ready flag. 64-bit accesses are single atomic LDG.64/STG.64.
__device__ volatile unsigned long long g_scale_packed;

// ---------------------------------------------------------------------------
// FINAL KERNEL (R15 config — measured 77.9us, 86.4% DRAM, 6851 GB/s, within
// 0.2% of the LTS-cap floor 537MB/6.9TB/s ≈ 77.8us; confirmed path-
// independent vs a TMA-bulk variant which hit the same ceiling).
//
// Single fused kernel, grid 4097:
//   block 0     : compute scale = max|W|/7, publish packed {s, 1/s}.
//   blocks 1..N : MaxPool3d(2) + int4-dequant linear(2048->4) + bias
//                 + softmax, 2 batch rows per block, CTA-cooperative
//                 contiguous sweeps.
// All 16 weight float2 are preloaded before the scale spin and dequantized
// once. x loads run a 2-deep pipeline: while processing iter k, loads for
// k+1 AND k+2 are in flight (16 LDG.128 outstanding per thread).
//
// Index: off(k) = loff + k*4096, loff = (t>>5)*512 + ((t>>2)&7)*32 + (t&3)*4.
// x layout: [B, C=4, D=16, H=16, W=16] f32, 16384 floats per row.
// 4 loads per feature-pair: off, off+16, off+256, off+272 (float4,
// sector-complete).
// ---------------------------------------------------------------------------
__global__ void __launch_bounds__(256)
fused_pool_linear_softmax_kernel(const float* __restrict__ x,
                                 const float* __restrict__ W,
                                 const float* __restrict__ bias,
                                 float* __restrict__ out) {
    const int t = threadIdx.x;

    // ---------------- block 0: scale producer ----------------
    if (blockIdx.x == 0) {
        __shared__ float s_warp[8];
        const float4* __restrict__ W4 = reinterpret_cast<const float4*>(W);
        float m = 0.0f;
        #pragma unroll
        for (int k = 0; k < 8; k++) {
            const float4 w = W4[t + k * 256];
            m = fmaxf(m, fmaxf(fmaxf(fabsf(w.x), fabsf(w.y)),
                               fmaxf(fabsf(w.z), fabsf(w.w))));
        }
        #pragma unroll
        for (int off = 16; off > 0; off >>= 1)
            m = fmaxf(m, __shfl_xor_sync(0xFFFFFFFFu, m, off));
        if ((t & 31) == 0) s_warp[t >> 5] = m;
        __syncthreads();
        if (t == 0) {
            float mm = fmaxf(fmaxf(fmaxf(s_warp[0], s_warp[1]),
                                   fmaxf(s_warp[2], s_warp[3])),
                             fmaxf(fmaxf(s_warp[4], s_warp[5]),
                                   fmaxf(s_warp[6], s_warp[7])));
            const float scale = mm / 7.0f;
            const float inv_scale = 1.0f / scale;
            const unsigned long long packed =
                ((unsigned long long)__float_as_uint(inv_scale) << 32) |
                (unsigned long long)__float_as_uint(scale);
            g_scale_packed = packed;   // volatile 64-bit store: flag == data
        }
        return;
    }

    // ---------------- blocks 1..4096: main body ----------------
    __shared__ float s_red[8][8];   // [warp][row0 accs 0..3 | row1 accs 4..7]

    const int b0 = (blockIdx.x - 1) * 2;
    const float* __restrict__ xb0 = x + (size_t)b0 * 16384;
    const float* __restrict__ xb1 = xb0 + 16384;

    const float4 bias4 = *reinterpret_cast<const float4*>(bias);

    float p0 = 0.0f, p1 = 0.0f, p2 = 0.0f, p3 = 0.0f;   // row 0 partials
    float q0 = 0.0f, q1 = 0.0f, q2 = 0.0f, q3 = 0.0f;   // row 1 partials

    const int loff = (t >> 5) * 512 + ((t >> 2) & 7) * 32 + (t & 3) * 4;
    const int wb   = t * 2;

    // ===== pre-spin: issue k=0 AND k=1 x loads, plus all weight loads =====
    const float4* pa0 = reinterpret_cast<const float4*>(xb0 + loff);
    const float4* pb0 = reinterpret_cast<const float4*>(xb1 + loff);
    float4 A0 = __ldcs(pa0);
    float4 A1 = __ldcs(pa0 + 4);
    float4 A2 = __ldcs(pa0 + 64);
    float4 A3 = __ldcs(pa0 + 68);
    float4 C0 = __ldcs(pb0);
    float4 C1 = __ldcs(pb0 + 4);
    float4 C2 = __ldcs(pb0 + 64);
    float4 C3 = __ldcs(pb0 + 68);

    const float4* pa1 = reinterpret_cast<const float4*>(xb0 + loff + 4096);
    const float4* pb1 = reinterpret_cast<const float4*>(xb1 + loff + 4096);
    float4 B0 = __ldcs(pa1);
    float4 B1 = __ldcs(pa1 + 4);
    float4 B2 = __ldcs(pa1 + 64);
    float4 B3 = __ldcs(pa1 + 68);
    float4 D0 = __ldcs(pb1);
    float4 D1 = __ldcs(pb1 + 4);
    float4 D2 = __ldcs(pb1 + 64);
    float4 D3 = __ldcs(pb1 + 68);

    // all weights for k=0..3, outputs 0..3 (scale-independent raw loads)
    float2 wv[4][4];   // wv[k][o]
    #pragma unroll
    for (int k = 0; k < 4; k++) {
        const int f2 = wb + k * 512;
        wv[k][0] = *reinterpret_cast<const float2*>(&W[f2]);
        wv[k][1] = *reinterpret_cast<const float2*>(&W[2048 + f2]);
        wv[k][2] = *reinterpret_cast<const float2*>(&W[4096 + f2]);
        wv[k][3] = *reinterpret_cast<const float2*>(&W[6144 + f2]);
    }

    // Spin for the packed scale; all loads above are in flight meanwhile.
    unsigned long long v = g_scale_packed;
    while (v == 0ull) v = g_scale_packed;
    const float scale     = __uint_as_float((unsigned int)v);
    const float inv_scale = __uint_as_float((unsigned int)(v >> 32));

    // dequantize all weights once (half-to-even; clip(-8,7) never binds)
    #pragma unroll
    for (int k = 0; k < 4; k++) {
        #pragma unroll
        for (int o = 0; o < 4; o++) {
            wv[k][o].x = rintf(wv[k][o].x * inv_scale) * scale;
            wv[k][o].y = rintf(wv[k][o].y * inv_scale) * scale;
        }
    }

    // ===== streaming loop, 2-deep pipeline =====
    // slot A/C holds even k, slot B/D holds odd k.
    #pragma unroll
    for (int k = 0; k < 4; k++) {
        float ma0, ma1, mb0, mb1;
        if ((k & 1) == 0) {
            ma0 = fmaxf(fmaxf(fmaxf(A0.x, A0.y), fmaxf(A1.x, A1.y)),
                        fmaxf(fmaxf(A2.x, A2.y), fmaxf(A3.x, A3.y)));
            ma1 = fmaxf(fmaxf(fmaxf(A0.z, A0.w), fmaxf(A1.z, A1.w)),
                        fmaxf(fmaxf(A2.z, A2.w), fmaxf(A3.z, A3.w)));
            mb0 = fmaxf(fmaxf(fmaxf(C0.x, C0.y), fmaxf(C1.x, C1.y)),
                        fmaxf(fmaxf(C2.x, C2.y), fmaxf(C3.x, C3.y)));
            mb1 = fmaxf(fmaxf(fmaxf(C0.z, C0.w), fmaxf(C1.z, C1.w)),
                        fmaxf(fmaxf(C2.z, C2.w), fmaxf(C3.z, C3.w)));
            // refill even slot with k+2
            if (k + 2 < 4) {
                const int off = loff + (k + 2) * 4096;
                const float4* pa = reinterpret_cast<const float4*>(xb0 + off);
                const float4* pb = reinterpret_cast<const float4*>(xb1 + off);
                A0 = __ldcs(pa);
                A1 = __ldcs(pa + 4);
                A2 = __ldcs(pa + 64);
                A3 = __ldcs(pa + 68);
                C0 = __ldcs(pb);
                C1 = __ldcs(pb + 4);
                C2 = __ldcs(pb + 64);
                C3 = __ldcs(pb + 68);
            }
        } else {
            ma0 = fmaxf(fmaxf(fmaxf(B0.x, B0.y), fmaxf(B1.x, B1.y)),
                        fmaxf(fmaxf(B2.x, B2.y), fmaxf(B3.x, B3.y)));
            ma1 = fmaxf(fmaxf(fmaxf(B0.z, B0.w), fmaxf(B1.z, B1.w)),
                        fmaxf(fmaxf(B2.z, B2.w), fmaxf(B3.z, B3.w)));
            mb0 = fmaxf(fmaxf(fmaxf(D0.x, D0.y), fmaxf(D1.x, D1.y)),
                        fmaxf(fmaxf(D2.x, D2.y), fmaxf(D3.x, D3.y)));
            mb1 = fmaxf(fmaxf(fmaxf(D0.z, D0.w), fmaxf(D1.z, D1.w)),
                        fmaxf(fmaxf(D2.z, D2.w), fmaxf(D3.z, D3.w)));
            // refill odd slot with k+2
            if (k + 2 < 4) {
                const int off = loff + (k + 2) * 4096;
                const float4* pa = reinterpret_cast<const float4*>(xb0 + off);
                const float4* pb = reinterpret_cast<const float4*>(xb1 + off);
                B0 = __ldcs(pa);
                B1 = __ldcs(pa + 4);
                B2 = __ldcs(pa + 64);
                B3 = __ldcs(pa + 68);
                D0 = __ldcs(pb);
                D1 = __ldcs(pb + 4);
                D2 = __ldcs(pb + 64);
                D3 = __ldcs(pb + 68);
            }
        }

        p0 = fmaf(ma0, wv[k][0].x, fmaf(ma1, wv[k][0].y, p0));
        p1 = fmaf(ma0, wv[k][1].x, fmaf(ma1, wv[k][1].y, p1));
        p2 = fmaf(ma0, wv[k][2].x, fmaf(ma1, wv[k][2].y, p2));
        p3 = fmaf(ma0, wv[k][3].x, fmaf(ma1, wv[k][3].y, p3));
        q0 = fmaf(mb0, wv[k][0].x, fmaf(mb1, wv[k][0].y, q0));
        q1 = fmaf(mb0, wv[k][1].x, fmaf(mb1, wv[k][1].y, q1));
        q2 = fmaf(mb0, wv[k][2].x, fmaf(mb1, wv[k][2].y, q2));
        q3 = fmaf(mb0, wv[k][3].x, fmaf(mb1, wv[k][3].y, q3));
    }

    // warp reduce all 8 accumulators
    #pragma unroll
    for (int off = 16; off > 0; off >>= 1) {
        p0 += __shfl_xor_sync(0xFFFFFFFFu, p0, off);
        p1 += __shfl_xor_sync(0xFFFFFFFFu, p1, off);
        p2 += __shfl_xor_sync(0xFFFFFFFFu, p2, off);
        p3 += __shfl_xor_sync(0xFFFFFFFFu, p3, off);
        q0 += __shfl_xor_sync(0xFFFFFFFFu, q0, off);
        q1 += __shfl_xor_sync(0xFFFFFFFFu, q1, off);
        q2 += __shfl_xor_sync(0xFFFFFFFFu, q2, off);
        q3 += __shfl_xor_sync(0xFFFFFFFFu, q3, off);
    }
    const int wid = t >> 5;
    if ((t & 31) == 0) {
        s_red[wid][0] = p0;  s_red[wid][1] = p1;
        s_red[wid][2] = p2;  s_red[wid][3] = p3;
        s_red[wid][4] = q0;  s_red[wid][5] = q1;
        s_red[wid][6] = q2;  s_red[wid][7] = q3;
    }
    __syncthreads();

    // threads 0 and 1 each finish one row
    if (t < 2) {
        const int base = t * 4;
        float l0 = bias4.x, l1 = bias4.y, l2 = bias4.z, l3 = bias4.w;
        #pragma unroll
        for (int w = 0; w < 8; w++) {
            l0 += s_red[w][base + 0];
            l1 += s_red[w][base + 1];
            l2 += s_red[w][base + 2];
            l3 += s_red[w][base + 3];
        }
        const float mx = fmaxf(fmaxf(l0, l1), fmaxf(l2, l3));
        const float e0 = __expf(l0 - mx);
        const float e1 = __expf(l1 - mx);
        const float e2 = __expf(l2 - mx);
        const float e3 = __expf(l3 - mx);
        const float inv = 1.0f / (e0 + e1 + e2 + e3);
        float4 r = make_float4(e0 * inv, e1 * inv, e2 * inv, e3 * inv);
        *reinterpret_cast<float4*>(out + (size_t)(b0 + t) * 4) = r;
    }
}

extern "C" void kernel_launch(void* const* d_in, const int* in_sizes, int n_in,
                              void* d_out, int out_size) {
    const float* x = (const float*)d_in[0];   // [8192,4,16,16,16]
    const float* W = (const float*)d_in[1];   // [4,2048]
    const float* b = (const float*)d_in[2];   // [4]
    float* out = (float*)d_out;               // [8192,4]

    fused_pool_linear_softmax_kernel<<<4097, 256>>>(x, W, b, out);
}